// round 1
// baseline (speedup 1.0000x reference)
#include <cuda_runtime.h>
#include <cstdint>

#define NN 20000
#define EE 640000
#define DD 64

// ---------------- device scratch (no allocations allowed) ----------------
__device__ float g_h[NN * DD];      // per-layer transformed features
__device__ float g_x1[NN * DD];     // layer-0 output (relu'd), layer-1 input
__device__ float g_s1[NN];          // per-source-node score term
__device__ int   g_row[EE];
__device__ int   g_col[EE];
__device__ int   g_srow[EE];        // source rows sorted by destination
__device__ int   g_cnt[NN];
__device__ int   g_off[NN + 1];
__device__ int   g_cur[NN];
__device__ int   g_is64;

// ---------------- preprocessing: detect dtype + zero counts ----------------
__global__ void k_detect_zero(const void* ei) {
    int t = blockIdx.x * blockDim.x + threadIdx.x;
    if (t < NN) g_cnt[t] = 0;
    if (t == 0) {
        // If the buffer is int32, reading as int64 combines two indices:
        // value = lo + hi*2^32 >= 2^32 unless hi == 0 (p = 1/20000).
        const long long* p = (const long long*)ei;
        int ok = 1;
        for (int k = 0; k < 64; k++) {
            long long v = p[k];
            if (v < 0 || v >= NN) { ok = 0; break; }
        }
        g_is64 = ok;
    }
}

__global__ void k_convert_hist(const void* ei) {
    int e = blockIdx.x * blockDim.x + threadIdx.x;
    if (e >= EE) return;
    int r, c;
    if (g_is64) {
        const long long* p = (const long long*)ei;
        r = (int)p[e];
        c = (int)p[EE + e];
    } else {
        const int* p = (const int*)ei;
        r = p[e];
        c = p[EE + e];
    }
    g_row[e] = r;
    g_col[e] = c;
    atomicAdd(&g_cnt[c], 1);
}

// single-block exclusive scan over NN counts -> g_off, g_cur
__global__ void k_scan() {
    __shared__ int sh[1024];
    int t = threadIdx.x;
    const int CH = (NN + 1023) / 1024;  // 20
    int base = t * CH;
    int s = 0;
#pragma unroll
    for (int i = 0; i < CH; i++) {
        int idx = base + i;
        if (idx < NN) s += g_cnt[idx];
    }
    sh[t] = s;
    __syncthreads();
    // Hillis-Steele inclusive scan of 1024 partials
    for (int off = 1; off < 1024; off <<= 1) {
        int v = (t >= off) ? sh[t - off] : 0;
        __syncthreads();
        sh[t] += v;
        __syncthreads();
    }
    int run = sh[t] - s;  // exclusive prefix of this chunk
    for (int i = 0; i < CH; i++) {
        int idx = base + i;
        if (idx < NN) {
            g_off[idx] = run;
            g_cur[idx] = run;
            run += g_cnt[idx];
        }
    }
    if (t == 1023) g_off[NN] = sh[1023];
}

__global__ void k_scatter() {
    int e = blockIdx.x * blockDim.x + threadIdx.x;
    if (e >= EE) return;
    int c = g_col[e];
    int p = atomicAdd(&g_cur[c], 1);
    g_srow[p] = g_row[e];
}

// ---------------- per-node bmm: h[n] = x[n] @ w[n], fused s1[n] ----------------
// one warp per node; lane owns output columns {2*lane, 2*lane+1}
__global__ void __launch_bounds__(256) k_bmm(const float* __restrict__ x_ext,
                                             const float* __restrict__ w,
                                             const float* __restrict__ att,
                                             int layer) {
    int wid  = (blockIdx.x * blockDim.x + threadIdx.x) >> 5;
    int lane = threadIdx.x & 31;
    if (wid >= NN) return;
    const float* x = layer ? g_x1 : x_ext;

    const float2* xn = (const float2*)(x + (size_t)wid * DD);
    const float2* wn = (const float2*)(w + (size_t)wid * DD * DD);
    float2 xv  = xn[lane];
    float2 acc = make_float2(0.f, 0.f);
#pragma unroll
    for (int dd = 0; dd < 32; dd++) {
        float xa = __shfl_sync(0xffffffffu, xv.x, dd);   // x[2*dd]
        float xb = __shfl_sync(0xffffffffu, xv.y, dd);   // x[2*dd+1]
        float2 w0 = wn[(2 * dd)     * 32 + lane];
        float2 w1 = wn[(2 * dd + 1) * 32 + lane];
        acc.x += xa * w0.x + xb * w1.x;
        acc.y += xa * w0.y + xb * w1.y;
    }
    ((float2*)g_h)[wid * 32 + lane] = acc;

    // s1[n] = h[n] . att[n, 0:64]   (source-only part of the edge score)
    const float2* an = (const float2*)(att + (size_t)wid * 2 * DD);
    float2 av = an[lane];
    float part = acc.x * av.x + acc.y * av.y;
#pragma unroll
    for (int o = 16; o; o >>= 1) part += __shfl_xor_sync(0xffffffffu, part, o);
    if (lane == 0) g_s1[wid] = part;
}

// ---------------- fused scores + online segment-softmax + aggregation ----------------
// one warp per destination node j
__global__ void __launch_bounds__(256) k_edge(const float* __restrict__ att,
                                              const float* __restrict__ bias,
                                              float* __restrict__ out_ext,
                                              int do_relu) {
    int j    = (blockIdx.x * blockDim.x + threadIdx.x) >> 5;
    int lane = threadIdx.x & 31;
    if (j >= NN) return;
    float* out = do_relu ? g_x1 : out_ext;

    int beg = g_off[j], end = g_off[j + 1];
    float2 bv = ((const float2*)bias)[lane];
    float2 res;
    if (beg == end) {
        res = bv;  // empty segment: softmax sum is 0, aggregate is 0
    } else {
        float2 hj = ((const float2*)g_h)[j * 32 + lane];
        float m = -1e30f, s = 0.f;
        float2 acc = make_float2(0.f, 0.f);
        for (int p = beg; p < end; p++) {
            int r = g_srow[p];
            // score(e) = s1[r] + h[j] . att[r, 64:128], then leaky_relu(0.2)
            const float2* ar = (const float2*)(att + (size_t)r * 2 * DD);
            float2 a2 = ar[32 + lane];
            float part = hj.x * a2.x + hj.y * a2.y;
#pragma unroll
            for (int o = 16; o; o >>= 1) part += __shfl_xor_sync(0xffffffffu, part, o);
            float score = g_s1[r] + part;
            score = (score >= 0.f) ? score : 0.2f * score;
            // online softmax update
            float mn = fmaxf(m, score);
            float cf = __expf(m - mn);      // rescale old accum (0 on first iter)
            float wv = __expf(score - mn);
            s = s * cf + wv;
            float2 hr = ((const float2*)g_h)[r * 32 + lane];
            acc.x = acc.x * cf + wv * hr.x;
            acc.y = acc.y * cf + wv * hr.y;
            m = mn;
        }
        float inv = 1.f / s;
        res.x = acc.x * inv + bv.x;
        res.y = acc.y * inv + bv.y;
    }
    if (do_relu) {
        res.x = fmaxf(res.x, 0.f);
        res.y = fmaxf(res.y, 0.f);
    }
    ((float2*)out)[j * 32 + lane] = res;
}

// ---------------- launch ----------------
extern "C" void kernel_launch(void* const* d_in, const int* in_sizes, int n_in,
                              void* d_out, int out_size) {
    const float* x    = (const float*)d_in[0];
    const void*  ei   = d_in[1];
    const float* w0   = (const float*)d_in[2];
    const float* att0 = (const float*)d_in[3];
    const float* b0   = (const float*)d_in[4];
    const float* w1   = (const float*)d_in[5];
    const float* att1 = (const float*)d_in[6];
    const float* b1   = (const float*)d_in[7];
    float* out = (float*)d_out;

    const int EB = (EE + 255) / 256;          // 2500
    const int NB = (NN * 32 + 255) / 256;     // 2500 blocks, warp per node
    const int ZB = (NN + 255) / 256;          // 79

    // shared preprocessing (both layers use the same edge structure)
    k_detect_zero<<<ZB, 256>>>(ei);
    k_convert_hist<<<EB, 256>>>(ei);
    k_scan<<<1, 1024>>>();
    k_scatter<<<EB, 256>>>();

    // layer 0
    k_bmm<<<NB, 256>>>(x, w0, att0, 0);
    k_edge<<<NB, 256>>>(att0, b0, nullptr, 1);   // writes relu(agg + b0) -> g_x1

    // layer 1
    k_bmm<<<NB, 256>>>(nullptr, w1, att1, 1);    // reads g_x1
    k_edge<<<NB, 256>>>(att1, b1, out, 0);       // writes agg + b1 -> d_out
}